// round 1
// baseline (speedup 1.0000x reference)
#include <cuda_runtime.h>

#define FULL 0xffffffffu

// ---- packed f32x2 helpers (Blackwell FFMA2 — only reachable via PTX) ----
__device__ __forceinline__ unsigned long long pk2(float lo, float hi) {
    unsigned long long r;
    asm("mov.b64 %0, {%1, %2};" : "=l"(r) : "f"(lo), "f"(hi));
    return r;
}
__device__ __forceinline__ float2 upk2(unsigned long long p) {
    float2 v;
    asm("mov.b64 {%0, %1}, %2;" : "=f"(v.x), "=f"(v.y) : "l"(p));
    return v;
}
__device__ __forceinline__ unsigned long long fma2(unsigned long long a,
                                                   unsigned long long b,
                                                   unsigned long long c) {
    unsigned long long d;
    asm("fma.rn.f32x2 %0, %1, %2, %3;" : "=l"(d) : "l"(a), "l"(b), "l"(c));
    return d;
}
__device__ __forceinline__ unsigned long long mul2(unsigned long long a,
                                                   unsigned long long b) {
    unsigned long long d;
    asm("mul.rn.f32x2 %0, %1, %2;" : "=l"(d) : "l"(a), "l"(b));
    return d;
}

// Fused kernel: per warp, 4 rows.
//   1) a[r][i] = x[r] . W1[i] + b1[i]           (i < 8; rest of FFN is dead code)
//   2) z_i = cos(th_i)cos(a_i) - sin(th_i)sin(ph_i)sin(a_i)   (closed-form qubit <Z>)
//      qout[0] = z1..z7 ; qout[i] = z0..zi      (CNOT ring conjugated to Z-strings)
//   3) out[r][e] = sum_q qout[q] * W2[e][q] + b2[e]
__global__ void __launch_bounds__(256, 2)
ffq_kernel(const float* __restrict__ x,  const float* __restrict__ W1,
           const float* __restrict__ b1, const float* __restrict__ qp,
           const float* __restrict__ W2, const float* __restrict__ b2,
           float* __restrict__ out, int nrows)
{
    const int lane = threadIdx.x & 31;
    const int wid  = threadIdx.x >> 5;
    const int gw   = blockIdx.x * 8 + wid;
    const int row0 = gw * 4;
    if (row0 >= nrows) return;

    const int qi = lane & 7;  // qubit index owned by this lane (after reduce-scatter)

    // per-qubit constants (accurate trig; computed once per thread)
    const float phi   = __ldg(qp + 3 * qi);
    const float theta = __ldg(qp + 3 * qi + 1);
    const float k1  = cosf(theta);
    const float k2  = sinf(theta) * sinf(phi);
    const float b1i = __ldg(b1 + qi);

    int rr[4];
#pragma unroll
    for (int r = 0; r < 4; r++) rr[r] = min(row0 + r, nrows - 1);

    // ---------------- GEMM1: 4 rows x 8 outputs, f32x2 packed along j ----------------
    unsigned long long acc[4][8];
#pragma unroll
    for (int r = 0; r < 4; r++)
#pragma unroll
        for (int i = 0; i < 8; i++) acc[r][i] = 0ull;

#pragma unroll
    for (int pos = 0; pos < 8; pos++) {
        const int j = pos * 128 + lane * 4;
        unsigned long long xA[4], xB[4];
#pragma unroll
        for (int r = 0; r < 4; r++) {
            float4 xv = __ldg((const float4*)(x + (size_t)rr[r] * 1024 + j));
            xA[r] = pk2(xv.x, xv.y);
            xB[r] = pk2(xv.z, xv.w);
        }
#pragma unroll
        for (int i = 0; i < 8; i++) {
            float4 w4 = __ldg((const float4*)(W1 + (size_t)i * 1024 + j));
            unsigned long long wA = pk2(w4.x, w4.y);
            unsigned long long wB = pk2(w4.z, w4.w);
#pragma unroll
            for (int r = 0; r < 4; r++) {
                acc[r][i] = fma2(xA[r], wA, acc[r][i]);
                acc[r][i] = fma2(xB[r], wB, acc[r][i]);
            }
        }
    }

    // fold f32x2 halves -> 32 scalars (index = r*8 + i)
    float v[32];
#pragma unroll
    for (int r = 0; r < 4; r++)
#pragma unroll
        for (int i = 0; i < 8; i++) {
            float2 t = upk2(acc[r][i]);
            v[r * 8 + i] = t.x + t.y;
        }

    // reduce-scatter across 32 lanes (31 shuffles): lane L ends with total of v-index L
#pragma unroll
    for (int w = 16; w >= 1; w >>= 1) {
        const bool hi = (lane & w) != 0;
#pragma unroll
        for (int k = 0; k < w; k++) {
            float sendv = hi ? v[k] : v[k + w];
            float keepv = hi ? v[k + w] : v[k];
            float recv  = __shfl_xor_sync(FULL, sendv, w, 32);
            v[k] = keepv + recv;
        }
    }

    // ---------------- closed-form quantum circuit ----------------
    const float a = v[0] + b1i;      // a for (row = lane>>3, qubit = lane&7)
    float sa, ca;
    __sincosf(a, &sa, &ca);
    const float z = k1 * ca - k2 * sa;

    // inclusive prefix product of z over each 8-lane octet
    float p = z;
#pragma unroll
    for (int d = 1; d < 8; d <<= 1) {
        float t = __shfl_up_sync(FULL, p, d, 8);
        if (qi >= d) p *= t;
    }
    // second scan with z0 -> 1 to get qout[0] = z1..z7
    float wv = (qi == 0) ? 1.0f : z;
#pragma unroll
    for (int d = 1; d < 8; d <<= 1) {
        float t = __shfl_up_sync(FULL, wv, d, 8);
        if (qi >= d) wv *= t;
    }
    const float pb7 = __shfl_sync(FULL, wv, 7, 8);
    const float qv  = (qi == 0) ? pb7 : p;   // qout[row = lane>>3][qi]

    // allgather all 32 qout values, pack into f32x2 pairs (q0q1, q2q3, q4q5, q6q7) per row
    unsigned long long qd[4][4];
#pragma unroll
    for (int r = 0; r < 4; r++)
#pragma unroll
        for (int pq = 0; pq < 4; pq++) {
            float g0 = __shfl_sync(FULL, qv, r * 8 + 2 * pq,     32);
            float g1 = __shfl_sync(FULL, qv, r * 8 + 2 * pq + 1, 32);
            qd[r][pq] = pk2(g0, g1);
        }

    // ---------------- GEMM2: out[r][e] = qout[r] . W2[e] + b2[e] ----------------
#pragma unroll 2
    for (int iter = 0; iter < 8; iter++) {
        const int e = iter * 128 + lane * 4;
        unsigned long long wp[4][4];
#pragma unroll
        for (int k = 0; k < 4; k++) {
            float4 wlo = __ldg((const float4*)(W2 + (size_t)(e + k) * 8));
            float4 whi = __ldg((const float4*)(W2 + (size_t)(e + k) * 8 + 4));
            wp[k][0] = pk2(wlo.x, wlo.y);
            wp[k][1] = pk2(wlo.z, wlo.w);
            wp[k][2] = pk2(whi.x, whi.y);
            wp[k][3] = pk2(whi.z, whi.w);
        }
        const float4 bv = __ldg((const float4*)(b2 + e));
#pragma unroll
        for (int r = 0; r < 4; r++) {
            if (row0 + r >= nrows) break;
            float o[4];
#pragma unroll
            for (int k = 0; k < 4; k++) {
                unsigned long long s = mul2(wp[k][0], qd[r][0]);
                s = fma2(wp[k][1], qd[r][1], s);
                s = fma2(wp[k][2], qd[r][2], s);
                s = fma2(wp[k][3], qd[r][3], s);
                float2 sv = upk2(s);
                o[k] = sv.x + sv.y;
            }
            float4 ov = make_float4(o[0] + bv.x, o[1] + bv.y, o[2] + bv.z, o[3] + bv.w);
            *((float4*)(out + (size_t)(row0 + r) * 1024 + e)) = ov;
        }
    }
}

extern "C" void kernel_launch(void* const* d_in, const int* in_sizes, int n_in,
                              void* d_out, int out_size)
{
    const float* x  = (const float*)d_in[0];
    const float* W1 = (const float*)d_in[1];
    const float* b1 = (const float*)d_in[2];
    const float* qp = (const float*)d_in[3];
    const float* W2 = (const float*)d_in[4];
    const float* b2 = (const float*)d_in[5];
    float* out = (float*)d_out;

    const int nrows = in_sizes[0] / 1024;          // batch * seq_len
    const int nblocks = (nrows + 31) / 32;         // 8 warps/block * 4 rows/warp

    ffq_kernel<<<nblocks, 256>>>(x, W1, b1, qp, W2, b2, out, nrows);
}

// round 2
// speedup vs baseline: 1.9251x; 1.9251x over previous
#include <cuda_runtime.h>

#define FULL 0xffffffffu

// ---- packed f32x2 helpers (Blackwell FFMA2 — only reachable via PTX) ----
__device__ __forceinline__ unsigned long long pk2(float lo, float hi) {
    unsigned long long r;
    asm("mov.b64 %0, {%1, %2};" : "=l"(r) : "f"(lo), "f"(hi));
    return r;
}
__device__ __forceinline__ float2 upk2(unsigned long long p) {
    float2 v;
    asm("mov.b64 {%0, %1}, %2;" : "=f"(v.x), "=f"(v.y) : "l"(p));
    return v;
}
__device__ __forceinline__ unsigned long long fma2(unsigned long long a,
                                                   unsigned long long b,
                                                   unsigned long long c) {
    unsigned long long d;
    asm("fma.rn.f32x2 %0, %1, %2, %3;" : "=l"(d) : "l"(a), "l"(b), "l"(c));
    return d;
}
__device__ __forceinline__ unsigned long long mul2(unsigned long long a,
                                                   unsigned long long b) {
    unsigned long long d;
    asm("mul.rn.f32x2 %0, %1, %2;" : "=l"(d) : "l"(a), "l"(b));
    return d;
}

// Two-phase fused kernel, 32 rows per 256-thread block.
// Phase 1 (per warp, 4 rows): a[r][i] = x[r].W1[i] + b1[i]  (i<8; rest of FFN dead)
//   closed-form qubit <Z>:  z_i = cos(th)cos(a) - sin(th)sin(phi)sin(a)
//   CNOT-ring conjugated to Z-strings:  qout[0]=z1..z7, qout[i]=z0..zi
//   -> qout for the block's 32 rows into smem.
// Phase 2 (per warp, fixed 128-wide e-chunk): W2 slice in regs ONCE, loop 32 rows:
//   out[row][e] = qout[row] . W2[e] + b2[e]   (coalesced STG.128)
__global__ void __launch_bounds__(256, 2)
ffq_kernel(const float* __restrict__ x,  const float* __restrict__ W1,
           const float* __restrict__ b1, const float* __restrict__ qp,
           const float* __restrict__ W2, const float* __restrict__ b2,
           float* __restrict__ out, int nrows)
{
    __shared__ float sq[32][8];   // qout for the block's 32 rows

    const int lane = threadIdx.x & 31;
    const int wid  = threadIdx.x >> 5;
    const int rowblk = blockIdx.x * 32;
    const int row0 = rowblk + wid * 4;

    const int qi = lane & 7;  // qubit index owned by this lane (after reduce-scatter)

    // ---------------- Phase 1: GEMM1 + quantum ----------------
    {
        const float phi   = __ldg(qp + 3 * qi);
        const float theta = __ldg(qp + 3 * qi + 1);
        const float k1  = cosf(theta);
        const float k2  = sinf(theta) * sinf(phi);
        const float b1i = __ldg(b1 + qi);

        int rr[4];
#pragma unroll
        for (int r = 0; r < 4; r++) rr[r] = min(row0 + r, nrows - 1);

        unsigned long long acc[4][8];
#pragma unroll
        for (int r = 0; r < 4; r++)
#pragma unroll
            for (int i = 0; i < 8; i++) acc[r][i] = 0ull;

#pragma unroll
        for (int pos = 0; pos < 8; pos++) {
            const int j = pos * 128 + lane * 4;
            unsigned long long xA[4], xB[4];
#pragma unroll
            for (int r = 0; r < 4; r++) {
                float4 xv = __ldg((const float4*)(x + (size_t)rr[r] * 1024 + j));
                xA[r] = pk2(xv.x, xv.y);
                xB[r] = pk2(xv.z, xv.w);
            }
#pragma unroll
            for (int i = 0; i < 8; i++) {
                float4 w4 = __ldg((const float4*)(W1 + (size_t)i * 1024 + j));
                unsigned long long wA = pk2(w4.x, w4.y);
                unsigned long long wB = pk2(w4.z, w4.w);
#pragma unroll
                for (int r = 0; r < 4; r++) {
                    acc[r][i] = fma2(xA[r], wA, acc[r][i]);
                    acc[r][i] = fma2(xB[r], wB, acc[r][i]);
                }
            }
        }

        // fold f32x2 halves -> 32 scalars (index = r*8 + i)
        float v[32];
#pragma unroll
        for (int r = 0; r < 4; r++)
#pragma unroll
            for (int i = 0; i < 8; i++) {
                float2 t = upk2(acc[r][i]);
                v[r * 8 + i] = t.x + t.y;
            }

        // reduce-scatter (31 shuffles): lane L ends with total of v-index L
#pragma unroll
        for (int w = 16; w >= 1; w >>= 1) {
            const bool hi = (lane & w) != 0;
#pragma unroll
            for (int k = 0; k < w; k++) {
                float sendv = hi ? v[k] : v[k + w];
                float keepv = hi ? v[k + w] : v[k];
                float recv  = __shfl_xor_sync(FULL, sendv, w, 32);
                v[k] = keepv + recv;
            }
        }

        // closed-form quantum circuit
        const float a = v[0] + b1i;   // a for (row = lane>>3, qubit = lane&7)
        float sa, ca;
        __sincosf(a, &sa, &ca);
        const float z = k1 * ca - k2 * sa;

        // inclusive prefix product of z over each 8-lane octet
        float p = z;
#pragma unroll
        for (int d = 1; d < 8; d <<= 1) {
            float t = __shfl_up_sync(FULL, p, d, 8);
            if (qi >= d) p *= t;
        }
        // second scan with z0 -> 1 to get qout[0] = z1..z7
        float wv = (qi == 0) ? 1.0f : z;
#pragma unroll
        for (int d = 1; d < 8; d <<= 1) {
            float t = __shfl_up_sync(FULL, wv, d, 8);
            if (qi >= d) wv *= t;
        }
        const float pb7 = __shfl_sync(FULL, wv, 7, 8);
        const float qv  = (qi == 0) ? pb7 : p;   // qout[row=row0+(lane>>3)][qi]

        sq[wid * 4 + (lane >> 3)][qi] = qv;
    }
    __syncthreads();

    // ---------------- Phase 2: GEMM2, W2 in regs, amortized over 32 rows ----------------
    const int e0 = wid * 128 + lane * 4;   // this lane's 4 output elements

    unsigned long long w2r[4][4];
#pragma unroll
    for (int k = 0; k < 4; k++) {
        float4 wlo = __ldg((const float4*)(W2 + (size_t)(e0 + k) * 8));
        float4 whi = __ldg((const float4*)(W2 + (size_t)(e0 + k) * 8 + 4));
        w2r[k][0] = pk2(wlo.x, wlo.y);
        w2r[k][1] = pk2(wlo.z, wlo.w);
        w2r[k][2] = pk2(whi.x, whi.y);
        w2r[k][3] = pk2(whi.z, whi.w);
    }
    const float4 bv = __ldg((const float4*)(b2 + e0));

#pragma unroll 4
    for (int rloc = 0; rloc < 32; rloc++) {
        const int row = rowblk + rloc;
        if (row >= nrows) break;

        const unsigned long long* sqp = (const unsigned long long*)sq[rloc];
        unsigned long long qd0 = sqp[0], qd1 = sqp[1], qd2 = sqp[2], qd3 = sqp[3];

        float o[4];
#pragma unroll
        for (int k = 0; k < 4; k++) {
            unsigned long long s = mul2(w2r[k][0], qd0);
            s = fma2(w2r[k][1], qd1, s);
            s = fma2(w2r[k][2], qd2, s);
            s = fma2(w2r[k][3], qd3, s);
            float2 sv = upk2(s);
            o[k] = sv.x + sv.y;
        }
        float4 ov = make_float4(o[0] + bv.x, o[1] + bv.y, o[2] + bv.z, o[3] + bv.w);
        *((float4*)(out + (size_t)row * 1024 + e0)) = ov;
    }
}

extern "C" void kernel_launch(void* const* d_in, const int* in_sizes, int n_in,
                              void* d_out, int out_size)
{
    const float* x  = (const float*)d_in[0];
    const float* W1 = (const float*)d_in[1];
    const float* b1 = (const float*)d_in[2];
    const float* qp = (const float*)d_in[3];
    const float* W2 = (const float*)d_in[4];
    const float* b2 = (const float*)d_in[5];
    float* out = (float*)d_out;

    const int nrows = in_sizes[0] / 1024;          // batch * seq_len
    const int nblocks = (nrows + 31) / 32;         // 8 warps * 4 rows each

    ffq_kernel<<<nblocks, 256>>>(x, W1, b1, qp, W2, b2, out, nrows);
}

// round 3
// speedup vs baseline: 1.9433x; 1.0095x over previous
#include <cuda_runtime.h>

#define FULL 0xffffffffu

// ---- packed f32x2 helpers (Blackwell FFMA2 — only reachable via PTX) ----
__device__ __forceinline__ unsigned long long pk2(float lo, float hi) {
    unsigned long long r;
    asm("mov.b64 %0, {%1, %2};" : "=l"(r) : "f"(lo), "f"(hi));
    return r;
}
__device__ __forceinline__ float2 upk2(unsigned long long p) {
    float2 v;
    asm("mov.b64 {%0, %1}, %2;" : "=f"(v.x), "=f"(v.y) : "l"(p));
    return v;
}
__device__ __forceinline__ unsigned long long fma2(unsigned long long a,
                                                   unsigned long long b,
                                                   unsigned long long c) {
    unsigned long long d;
    asm("fma.rn.f32x2 %0, %1, %2, %3;" : "=l"(d) : "l"(a), "l"(b), "l"(c));
    return d;
}
__device__ __forceinline__ unsigned long long mul2(unsigned long long a,
                                                   unsigned long long b) {
    unsigned long long d;
    asm("mul.rn.f32x2 %0, %1, %2;" : "=l"(d) : "l"(a), "l"(b));
    return d;
}

// Split-K fused kernel, 16 rows per 256-thread block, grid 512.
// Phase 1 (split-K GEMM1): warp w owns j-slice [w*128, w*128+128); its W1 slice
//   (8 outputs x 4 j per lane) is register-resident for the whole block. Per row:
//   1 x-LDG.128, 16 fma2, 9-shuffle lane reduction, 8-float smem partial.
// Quantum (threads 0..127, one per (row,qubit)): sum 8 warp partials, then
//   closed form z = cos(th)cos(a) - sin(th)sin(phi)sin(a); CNOT ring conjugated
//   to Z-strings -> qout[0]=z1..z7, qout[i]=z0..zi via octet prefix products.
// Phase 2 (GEMM2): lane handles e = wid*128 + c*32 + lane (c=0..3) so W2 loads
//   are contiguous 1KB per warp; W2 register-resident per block; 16-row loop.
__global__ void __launch_bounds__(256, 3)
ffq_kernel(const float* __restrict__ x,  const float* __restrict__ W1,
           const float* __restrict__ b1, const float* __restrict__ qp,
           const float* __restrict__ W2, const float* __restrict__ b2,
           float* __restrict__ out, int nrows)
{
    __shared__ float part[16][8][8];   // [row][qubit][warp] partial dots
    __shared__ float sq[16][8];        // qout per row

    const int lane = threadIdx.x & 31;
    const int wid  = threadIdx.x >> 5;
    const int rowblk = blockIdx.x * 16;

    // ---------------- Phase 1: split-K GEMM1 ----------------
    {
        const int j0 = wid * 128 + lane * 4;   // this lane's 4 j's
        unsigned long long wp[8][2];           // W1[i][j0..j0+3], packed, reg-resident
#pragma unroll
        for (int i = 0; i < 8; i++) {
            float4 w4 = __ldg((const float4*)(W1 + (size_t)i * 1024 + j0));
            wp[i][0] = pk2(w4.x, w4.y);
            wp[i][1] = pk2(w4.z, w4.w);
        }

#pragma unroll 4
        for (int rloc = 0; rloc < 16; rloc++) {
            const int row = min(rowblk + rloc, nrows - 1);
            float4 xv = __ldg((const float4*)(x + (size_t)row * 1024 + j0));
            unsigned long long xp0 = pk2(xv.x, xv.y);
            unsigned long long xp1 = pk2(xv.z, xv.w);

            float v[8];
#pragma unroll
            for (int i = 0; i < 8; i++) {
                unsigned long long s = mul2(xp0, wp[i][0]);
                s = fma2(xp1, wp[i][1], s);
                float2 f = upk2(s);
                v[i] = f.x + f.y;
            }

            // reduce-scatter over lane bits 0..2: lane L -> index L&7
#pragma unroll
            for (int w = 4; w >= 1; w >>= 1) {
                const bool hi = (lane & w) != 0;
#pragma unroll
                for (int k = 0; k < w; k++) {
                    float sendv = hi ? v[k] : v[k + w];
                    float keepv = hi ? v[k + w] : v[k];
                    v[k] = keepv + __shfl_xor_sync(FULL, sendv, w, 32);
                }
            }
            // fold the 4 octets
            float s8 = v[0];
            s8 += __shfl_xor_sync(FULL, s8, 8, 32);
            s8 += __shfl_xor_sync(FULL, s8, 16, 32);

            if (lane < 8) part[rloc][lane][wid] = s8;
        }
    }
    __syncthreads();

    // ---------------- Quantum: one thread per (row, qubit) ----------------
    if (threadIdx.x < 128) {
        const int row = threadIdx.x >> 3;
        const int qi  = threadIdx.x & 7;

        const float4 pa = *(const float4*)&part[row][qi][0];
        const float4 pb = *(const float4*)&part[row][qi][4];
        const float a = ((pa.x + pa.y) + (pa.z + pa.w))
                      + ((pb.x + pb.y) + (pb.z + pb.w)) + __ldg(b1 + qi);

        const float phi   = __ldg(qp + 3 * qi);
        const float theta = __ldg(qp + 3 * qi + 1);
        const float k1 = cosf(theta);
        const float k2 = sinf(theta) * sinf(phi);

        float sa, ca;
        __sincosf(a, &sa, &ca);
        const float z = k1 * ca - k2 * sa;

        // inclusive prefix product over each 8-lane octet
        float p = z;
#pragma unroll
        for (int d = 1; d < 8; d <<= 1) {
            float t = __shfl_up_sync(FULL, p, d, 8);
            if (qi >= d) p *= t;
        }
        // second scan with z0 -> 1 for qout[0] = z1..z7
        float wv = (qi == 0) ? 1.0f : z;
#pragma unroll
        for (int d = 1; d < 8; d <<= 1) {
            float t = __shfl_up_sync(FULL, wv, d, 8);
            if (qi >= d) wv *= t;
        }
        const float pb7 = __shfl_sync(FULL, wv, 7, 8);
        sq[row][qi] = (qi == 0) ? pb7 : p;
    }
    __syncthreads();

    // ---------------- Phase 2: GEMM2, W2 reg-resident, contiguous loads ----------------
    // lane handles e_c = wid*128 + c*32 + lane, c = 0..3
    unsigned long long w2r[4][4];
    float bv[4];
#pragma unroll
    for (int c = 0; c < 4; c++) {
        const int e = wid * 128 + c * 32 + lane;
        float4 wlo = __ldg((const float4*)(W2 + (size_t)e * 8));
        float4 whi = __ldg((const float4*)(W2 + (size_t)e * 8 + 4));
        w2r[c][0] = pk2(wlo.x, wlo.y);
        w2r[c][1] = pk2(wlo.z, wlo.w);
        w2r[c][2] = pk2(whi.x, whi.y);
        w2r[c][3] = pk2(whi.z, whi.w);
        bv[c] = __ldg(b2 + e);
    }

#pragma unroll 4
    for (int rloc = 0; rloc < 16; rloc++) {
        const int row = rowblk + rloc;
        if (row >= nrows) break;

        const unsigned long long* sqp = (const unsigned long long*)sq[rloc];
        unsigned long long qd0 = sqp[0], qd1 = sqp[1], qd2 = sqp[2], qd3 = sqp[3];

        float* orow = out + (size_t)row * 1024 + wid * 128 + lane;
#pragma unroll
        for (int c = 0; c < 4; c++) {
            unsigned long long s = mul2(w2r[c][0], qd0);
            s = fma2(w2r[c][1], qd1, s);
            s = fma2(w2r[c][2], qd2, s);
            s = fma2(w2r[c][3], qd3, s);
            float2 sv = upk2(s);
            orow[c * 32] = (sv.x + sv.y) + bv[c];
        }
    }
}

extern "C" void kernel_launch(void* const* d_in, const int* in_sizes, int n_in,
                              void* d_out, int out_size)
{
    const float* x  = (const float*)d_in[0];
    const float* W1 = (const float*)d_in[1];
    const float* b1 = (const float*)d_in[2];
    const float* qp = (const float*)d_in[3];
    const float* W2 = (const float*)d_in[4];
    const float* b2 = (const float*)d_in[5];
    float* out = (float*)d_out;

    const int nrows = in_sizes[0] / 1024;            // batch * seq_len
    const int nblocks = (nrows + 15) / 16;           // 16 rows per block

    ffq_kernel<<<nblocks, 256>>>(x, W1, b1, qp, W2, b2, out, nrows);
}